// round 17
// baseline (speedup 1.0000x reference)
#include <cuda_runtime.h>
#include <cuda_bf16.h>

#define FULL 0xffffffffu
#define MAXB 4096
#define FDIM 168   // [0:32) accp | [32:64) accc | [64:165) counts | pad
#define FOLD_BLOCKS 43

// ---- device scratch (static: no allocation anywhere) ----
// One struct so a single memsetAsync resets accum + counters.
struct Scratch {
    float accum[MAXB * FDIM];
    int   cnt[MAXB];        // per-row completed-chunk counters
    int   foldcnt;          // fold-blocks-done counter
};
__device__ Scratch g_s;
__device__ float g_G[FDIM * 64];   // folded weight matrix (rebuilt every replay)
__device__ float g_b1[64];         // folded fc1 bias

// ============================================================
// Fold (validated R7/R11/R12): G[168x64], b1[64].
// f layout: [0:32) u_p | [32:64) u_c | [64:115) cnt_p | [115:165) cnt_c
// ============================================================
__device__ void fold_work(int gid,
                          const float* __restrict__ w_p2, const float* __restrict__ b_p2,
                          const float* __restrict__ w_c2, const float* __restrict__ b_c2,
                          const float* __restrict__ emb_gender, const float* __restrict__ emb_korean,
                          const float* __restrict__ emb_primary, const float* __restrict__ emb_job,
                          const float* __restrict__ emb_rep, const float* __restrict__ emb_place,
                          const float* __restrict__ emb_add,
                          const float* __restrict__ w_fc1, const float* __restrict__ b_fc1)
{
    if (gid >= 169 * 64) return;
    const int v = gid >> 6;
    const int j = gid & 63;

    if (v < 32) {
        float s = 0.f;
        #pragma unroll
        for (int d = 0; d < 32; d++)
            s = fmaf(w_p2[v * 32 + d], w_fc1[(64 + d) * 64 + j], s);
        g_G[v * 64 + j] = s;
    } else if (v < 64) {
        const int e = v - 32;
        float s = 0.f;
        #pragma unroll
        for (int d = 0; d < 32; d++)
            s = fmaf(w_c2[e * 32 + d], w_fc1[(96 + d) * 64 + j], s);
        g_G[v * 64 + j] = s;
    } else if (v < 115) {
        const int vv = v - 64;
        const float* er;
        if      (vv < 2)  er = emb_gender  + vv * 32;
        else if (vv < 4)  er = emb_korean  + (vv - 2) * 32;
        else if (vv < 6)  er = emb_primary + (vv - 4) * 32;
        else if (vv < 17) er = emb_job     + (vv - 6) * 32;
        else              er = emb_rep     + (vv - 17) * 32;
        float s = 0.f;
        #pragma unroll
        for (int d = 0; d < 32; d++)
            s = fmaf(er[d], w_fc1[d * 64 + j], s);
        g_G[v * 64 + j] = s;
    } else if (v < 165) {
        const int cc = v - 115;
        const float* er = (cc < 19) ? (emb_place + cc * 32) : (emb_add + (cc - 19) * 32);
        float s = 0.f;
        #pragma unroll
        for (int d = 0; d < 32; d++)
            s = fmaf(er[d], w_fc1[(32 + d) * 64 + j], s);
        g_G[v * 64 + j] = s;
    } else if (v < FDIM) {
        g_G[v * 64 + j] = 0.f;
    } else {                      // v == 168: folded bias
        float s = b_fc1[j];
        #pragma unroll
        for (int d = 0; d < 32; d++) {
            s = fmaf(b_p2[d], w_fc1[(64 + d) * 64 + j], s);
            s = fmaf(b_c2[d], w_fc1[(96 + d) * 64 + j], s);
        }
        g_b1[j] = s;
    }
}

__device__ __forceinline__ void hupd_g(float* fr, int base, int idx, int lane) {
    unsigned m = __match_any_sync(FULL, idx);
    int leader = __ffs(m) - 1;
    if (lane == leader && idx != 999) {
        atomicAdd(fr + base + idx, (float)__popc(m));
    }
}

// ============================================================
// kA': 43 leading fold blocks (wave 1; signal foldcnt), then one
// warp per (row, chunk) with RED.ADD into accum. The LAST
// finishing chunk-warp of each row runs the row's epilogue
// inline: F = scaled accum row; out = relu(relu(F@G+b1)@w_fc2+b_fc2).
// Count layout (101): gender@0(2) korean@2(2) primary@4(2)
// job@6(11) rep@17(34) place@51(19) add@70(31)
// ============================================================
__global__ void __launch_bounds__(256)
ka_fused(const float* __restrict__ cont_p, const float* __restrict__ cont_c,
         const int* __restrict__ cat_p, const int* __restrict__ cat_c,
         const int* __restrict__ lengths,
         const float* __restrict__ w_p1, const float* __restrict__ b_p1,
         const float* __restrict__ w_c1, const float* __restrict__ b_c1,
         const float* __restrict__ w_p2, const float* __restrict__ b_p2,
         const float* __restrict__ w_c2, const float* __restrict__ b_c2,
         const float* __restrict__ emb_gender, const float* __restrict__ emb_korean,
         const float* __restrict__ emb_primary, const float* __restrict__ emb_job,
         const float* __restrict__ emb_rep, const float* __restrict__ emb_place,
         const float* __restrict__ emb_add,
         const float* __restrict__ w_fc1, const float* __restrict__ b_fc1,
         const float* __restrict__ w_fc2, const float* __restrict__ b_fc2,
         float* __restrict__ out,
         int S, int B, int smax)
{
    __shared__ float4 stX[8][32];    // (p0, c0, p1, c1)
    __shared__ float2 stY[8][32];    // (p2, 0)
    __shared__ float  stE[8][FDIM];  // per-warp epilogue F slice

    // Leading blocks: fold, then signal completion.
    if (blockIdx.x < FOLD_BLOCKS) {
        fold_work(blockIdx.x * 256 + threadIdx.x, w_p2, b_p2, w_c2, b_c2,
                  emb_gender, emb_korean, emb_primary, emb_job, emb_rep,
                  emb_place, emb_add, w_fc1, b_fc1);
        __syncthreads();
        if (threadIdx.x == 0) {
            __threadfence();
            atomicAdd(&g_s.foldcnt, 1);
        }
        return;
    }

    const int lane = threadIdx.x & 31;
    const int wib  = threadIdx.x >> 5;
    const int g    = (blockIdx.x - FOLD_BLOCKS) * 8 + wib;
    const int row  = g / smax;
    const int chunk = g - row * smax;
    if (row >= B) return;

    const int len = lengths[row];
    const int t0  = chunk * 32;
    if (t0 >= len) return;                           // dead chunk: fast exit

    const int nv = min(32, len - t0);
    const bool valid = lane < nv;
    const int rowbase = row * S;
    const int t = t0 + lane;

    float p0 = 0.f, p1 = 0.f, p2 = 0.f, c0 = 0.f, c1 = 0.f;
    int i0 = 999, i1 = 999, i2 = 999, i3 = 999, i4 = 999, j0 = 999, j1 = 999;
    if (valid) {
        const float* cp = cont_p + (rowbase + t) * 3;
        p0 = cp[0]; p1 = cp[1]; p2 = cp[2];
        float2 cc = *reinterpret_cast<const float2*>(cont_c + (rowbase + t) * 2);
        c0 = cc.x; c1 = cc.y;
        const int* ip = cat_p + (rowbase + t) * 5;
        i0 = ip[0]; i1 = ip[1]; i2 = ip[2]; i3 = ip[3]; i4 = ip[4];
        int2 jc = *reinterpret_cast<const int2*>(cat_c + (rowbase + t) * 2);
        j0 = jc.x; j1 = jc.y;
    }

    stX[wib][lane] = make_float4(p0, c0, p1, c1);
    stY[wib][lane] = make_float2(p2, 0.f);

    float* fr = g_s.accum + row * FDIM;

    hupd_g(fr, 64 +  0, i0, lane);
    hupd_g(fr, 64 +  2, i1, lane);
    hupd_g(fr, 64 +  4, i2, lane);
    hupd_g(fr, 64 +  6, i3, lane);
    hupd_g(fr, 64 + 17, i4, lane);
    hupd_g(fr, 64 + 51, j0, lane);
    hupd_g(fr, 64 + 70, j1, lane);

    const float wp0 = w_p1[lane];
    const float wp1 = w_p1[32 + lane];
    const float wp2 = w_p1[64 + lane];
    const float bp  = b_p1[lane];
    const float wc0 = w_c1[lane];
    const float wc1 = w_c1[32 + lane];
    const float bc  = b_c1[lane];

    __syncwarp();

    float ap0 = 0.f, ap1 = 0.f, ac0 = 0.f, ac1 = 0.f;
    int j = 0;
    #pragma unroll 4
    for (; j + 2 <= nv; j += 2) {
        const float4 xA = stX[wib][j];
        const float2 yA = stY[wib][j];
        const float4 xB = stX[wib][j + 1];
        const float2 yB = stY[wib][j + 1];
        ap0 += fmaxf(fmaf(yA.x, wp2, fmaf(xA.z, wp1, fmaf(xA.x, wp0, bp))), 0.f);
        ac0 += fmaxf(fmaf(xA.w, wc1, fmaf(xA.y, wc0, bc)), 0.f);
        ap1 += fmaxf(fmaf(yB.x, wp2, fmaf(xB.z, wp1, fmaf(xB.x, wp0, bp))), 0.f);
        ac1 += fmaxf(fmaf(xB.w, wc1, fmaf(xB.y, wc0, bc)), 0.f);
    }
    if (j < nv) {
        const float4 xA = stX[wib][j];
        const float2 yA = stY[wib][j];
        ap0 += fmaxf(fmaf(yA.x, wp2, fmaf(xA.z, wp1, fmaf(xA.x, wp0, bp))), 0.f);
        ac0 += fmaxf(fmaf(xA.w, wc1, fmaf(xA.y, wc0, bc)), 0.f);
    }

    atomicAdd(fr + lane,      ap0 + ap1);
    atomicAdd(fr + 32 + lane, ac0 + ac1);

    // ---- last-finisher election ----
    __threadfence();   // order this warp's RED.ADDs before counter bump
    int done = 0;
    if (lane == 0) done = atomicAdd(&g_s.cnt[row], 1);
    done = __shfl_sync(FULL, done, 0);
    const int liveChunks = (len + 31) >> 5;
    if (done != liveChunks - 1) return;

    // ---- inline epilogue for this row (runs exactly once per row) ----
    // Wait for fold completion (fold blocks are 0..42, wave-1 resident).
    if (lane == 0) {
        while (*((volatile int*)&g_s.foldcnt) != FOLD_BLOCKS) { }
    }
    __syncwarp();
    __threadfence();   // acquire: counter observation -> fr/G reads

    // Stage scaled F (L1-bypass loads; data is L2-resident from atomics).
    const float il = 1.0f / (float)len;
    for (int i = lane; i < FDIM; i += 32) {
        const float v = __ldcg(fr + i);
        const float sc = (i < 64) ? il : (i < 115) ? il * 0.2f
                          : (i < 165) ? il * 0.5f : 0.f;
        stE[wib][i] = v * sc;
    }
    __syncwarp();

    // GEMV: lane owns fc1 output pair (2*lane, 2*lane+1).
    const int j2 = lane * 2;
    float a0a = 0.f, a0b = 0.f, a1a = 0.f, a1b = 0.f;
    #pragma unroll 6
    for (int k = 0; k < FDIM; k += 2) {
        const float2 f01 = *reinterpret_cast<const float2*>(&stE[wib][k]);
        const float2 g0  = *reinterpret_cast<const float2*>(&g_G[k * 64 + j2]);
        const float2 g1  = *reinterpret_cast<const float2*>(&g_G[(k + 1) * 64 + j2]);
        a0a = fmaf(f01.x, g0.x, a0a);
        a1a = fmaf(f01.x, g0.y, a1a);
        a0b = fmaf(f01.y, g1.x, a0b);
        a1b = fmaf(f01.y, g1.y, a1b);
    }

    const float2 b1v = *reinterpret_cast<const float2*>(&g_b1[j2]);
    const float h0 = fmaxf(a0a + a0b + b1v.x, 0.f);
    const float h1 = fmaxf(a1a + a1b + b1v.y, 0.f);

    // fc2: w_fc2 [64][2] row-major; lane's 2 j's = 4 consecutive floats.
    const float4 w2 = *reinterpret_cast<const float4*>(w_fc2 + j2 * 2);
    float s0 = h0 * w2.x + h1 * w2.z;
    float s1 = h0 * w2.y + h1 * w2.w;

    #pragma unroll
    for (int m = 16; m; m >>= 1) {
        s0 += __shfl_xor_sync(FULL, s0, m);
        s1 += __shfl_xor_sync(FULL, s1, m);
    }

    if (lane == 0) {
        float2 o;
        o.x = fmaxf(s0 + b_fc2[0], 0.f);
        o.y = fmaxf(s1 + b_fc2[1], 0.f);
        reinterpret_cast<float2*>(out)[row] = o;
    }
}

extern "C" void kernel_launch(void* const* d_in, const int* in_sizes, int n_in,
                              void* d_out, int out_size)
{
    const float* cont_p   = (const float*)d_in[0];
    const float* cont_c   = (const float*)d_in[1];
    const int*   cat_p    = (const int*)  d_in[2];
    const int*   cat_c    = (const int*)  d_in[3];
    const int*   lengths  = (const int*)  d_in[4];
    const float* w_p1     = (const float*)d_in[5];
    const float* b_p1     = (const float*)d_in[6];
    const float* w_p2     = (const float*)d_in[7];
    const float* b_p2     = (const float*)d_in[8];
    const float* w_c1     = (const float*)d_in[9];
    const float* b_c1     = (const float*)d_in[10];
    const float* w_c2     = (const float*)d_in[11];
    const float* b_c2     = (const float*)d_in[12];
    const float* emb_gender  = (const float*)d_in[13];
    const float* emb_korean  = (const float*)d_in[14];
    const float* emb_primary = (const float*)d_in[15];
    const float* emb_job     = (const float*)d_in[16];
    const float* emb_rep     = (const float*)d_in[17];
    const float* emb_place   = (const float*)d_in[18];
    const float* emb_add     = (const float*)d_in[19];
    const float* w_fc1    = (const float*)d_in[20];
    const float* b_fc1    = (const float*)d_in[21];
    const float* w_fc2    = (const float*)d_in[22];
    const float* b_fc2    = (const float*)d_in[23];
    float* out = (float*)d_out;

    const int B = in_sizes[4];                 // lengths: [B]
    const int S = in_sizes[0] / (B * 3);       // cont_p: [B,S,3]
    const int smax = (S + 31) / 32;

    // One memset resets accum + per-row counters + fold counter.
    void* scratch_ptr = nullptr;
    cudaGetSymbolAddress(&scratch_ptr, g_s);
    cudaMemsetAsync(scratch_ptr, 0, sizeof(Scratch));

    const int chunkBlocks = (B * smax + 7) / 8;
    ka_fused<<<FOLD_BLOCKS + chunkBlocks, 256>>>(
        cont_p, cont_c, cat_p, cat_c, lengths,
        w_p1, b_p1, w_c1, b_c1,
        w_p2, b_p2, w_c2, b_c2,
        emb_gender, emb_korean, emb_primary, emb_job, emb_rep,
        emb_place, emb_add, w_fc1, b_fc1, w_fc2, b_fc2,
        out, S, B, smax);
}